// round 1
// baseline (speedup 1.0000x reference)
#include <cuda_runtime.h>
#include <math.h>

#define B_ 512
#define T_ 512

// Scratch (static __device__ arrays: allocation-free per harness rules)
__device__ float g_bufA[(size_t)T_ * B_ * 70];   // xw of current layer
__device__ float g_bufB[(size_t)T_ * B_ * 64];   // hidden sequence of layers 0..2
__device__ float g_hlast[B_ * 70];

// ---------------------------------------------------------------------------
// GEMM: out[r, n] = sum_k inrow(r)[k] * W[k][n] + bias[n],  r = t*B_ + b
// out is time-major [T, B, N]. For layer 0 (L0=true) the input is x [B, T, K].
// A tile stored k-major in smem -> float4 loads of 4 rows; W float4 over cols.
// ---------------------------------------------------------------------------
template <int K, int N, int TM, bool L0>
__global__ void __launch_bounds__(((N + 3) / 4) * (TM / 4))
gemm_kernel(const float* __restrict__ in, const float* __restrict__ W,
            const float* __restrict__ bias, float* __restrict__ out) {
    constexpr int NG4 = (N + 3) / 4;   // float4 col groups
    constexpr int NP  = NG4 * 4;       // padded N
    constexpr int TMP = TM + 4;        // padded row stride (16B-aligned rows)

    __shared__ __align__(16) float AshT[K * TMP];  // [k][row]
    __shared__ __align__(16) float Wsh[K * NP];    // [k][col] padded

    const int tid  = threadIdx.x;
    const int nthr = blockDim.x;
    const int rM   = blockIdx.x * TM;

    // Load W with zero padding
    for (int idx = tid; idx < K * NP; idx += nthr) {
        int k = idx / NP, c = idx % NP;
        Wsh[idx] = (c < N) ? W[k * N + c] : 0.f;
    }
    // Load A tile transposed into smem
    for (int idx = tid; idx < TM * K; idx += nthr) {
        int rr = idx / K, kk = idx % K;
        int r = rM + rr;
        size_t g;
        if (L0) {
            int t = r >> 9;          // r / B_
            int b = r & (B_ - 1);    // r % B_
            g = ((size_t)b * T_ + t) * K + kk;   // x is [B, T, K]
        } else {
            g = (size_t)r * K + kk;              // time-major [T*B, K]
        }
        AshT[kk * TMP + rr] = in[g];
    }
    __syncthreads();

    const int tx  = tid % NG4;       // col group
    const int rid = tid / NG4;       // row group (4 rows)
    const int colb = 4 * tx;

    float4 bv;
    bv.x = (colb + 0 < N) ? bias[colb + 0] : 0.f;
    bv.y = (colb + 1 < N) ? bias[colb + 1] : 0.f;
    bv.z = (colb + 2 < N) ? bias[colb + 2] : 0.f;
    bv.w = (colb + 3 < N) ? bias[colb + 3] : 0.f;
    float4 acc0 = bv, acc1 = bv, acc2 = bv, acc3 = bv;

    const float4* Wp = (const float4*)Wsh;
#pragma unroll 4
    for (int k = 0; k < K; k++) {
        float4 a = *(const float4*)&AshT[k * TMP + rid * 4];
        float4 w = Wp[k * NG4 + tx];
        acc0.x = fmaf(a.x, w.x, acc0.x); acc0.y = fmaf(a.x, w.y, acc0.y);
        acc0.z = fmaf(a.x, w.z, acc0.z); acc0.w = fmaf(a.x, w.w, acc0.w);
        acc1.x = fmaf(a.y, w.x, acc1.x); acc1.y = fmaf(a.y, w.y, acc1.y);
        acc1.z = fmaf(a.y, w.z, acc1.z); acc1.w = fmaf(a.y, w.w, acc1.w);
        acc2.x = fmaf(a.z, w.x, acc2.x); acc2.y = fmaf(a.z, w.y, acc2.y);
        acc2.z = fmaf(a.z, w.z, acc2.z); acc2.w = fmaf(a.z, w.w, acc2.w);
        acc3.x = fmaf(a.w, w.x, acc3.x); acc3.y = fmaf(a.w, w.y, acc3.y);
        acc3.z = fmaf(a.w, w.z, acc3.z); acc3.w = fmaf(a.w, w.w, acc3.w);
    }

    float4 accs[4] = {acc0, acc1, acc2, acc3};
#pragma unroll
    for (int r = 0; r < 4; r++) {
        size_t row = (size_t)(rM + rid * 4 + r);
        if constexpr (N % 4 == 0) {
            *(float4*)&out[row * N + colb] = accs[r];
        } else {
            float v[4] = {accs[r].x, accs[r].y, accs[r].z, accs[r].w};
#pragma unroll
            for (int c = 0; c < 4; c++)
                if (colb + c < N) out[row * N + colb + c] = v[c];
        }
    }
}

// ---------------------------------------------------------------------------
// Recurrent scan: h_t = tanh(xw_t + h_{t-1} @ U), h_0 = 0.
// Block handles NB batch elements; thread (bl, j) owns output unit j of batch
// element bl. U column j in registers; h double-buffered in shared.
// xw is time-major [T, B, H]; WS ? write hseq [T, B, H] : write h_last [B, H].
// ---------------------------------------------------------------------------
template <int H, int NB, bool WS>
__global__ void __launch_bounds__(NB * H)
scan_kernel(const float* __restrict__ xw, const float* __restrict__ U,
            float* __restrict__ out) {
    constexpr int HP = (H + 3) / 4 * 4;
    __shared__ __align__(16) float hsh[2][NB][HP];

    const int tid = threadIdx.x;
    const int bl  = tid / H;
    const int j   = tid % H;
    const int b   = blockIdx.x * NB + bl;

    // U column j -> registers (zero-padded)
    float u[HP];
#pragma unroll
    for (int i = 0; i < HP; i++) u[i] = (i < H) ? U[i * H + j] : 0.f;

    // zero both h buffers (incl. padding, which is never rewritten)
    for (int idx = tid; idx < 2 * NB * HP; idx += blockDim.x)
        (&hsh[0][0][0])[idx] = 0.f;
    __syncthreads();

    const float* xp = xw + (size_t)b * H + j;
    float* op = out + (size_t)b * H + j;

    int cur = 0;
    for (int t = 0; t < T_; t++) {
        float acc0 = xp[(size_t)t * B_ * H];
        float acc1 = 0.f;
        const float4* h4 = (const float4*)&hsh[cur][bl][0];
#pragma unroll
        for (int i = 0; i < HP / 4; i++) {
            float4 hv = h4[i];
            acc0 = fmaf(hv.x, u[4 * i + 0], acc0);
            acc1 = fmaf(hv.y, u[4 * i + 1], acc1);
            acc0 = fmaf(hv.z, u[4 * i + 2], acc0);
            acc1 = fmaf(hv.w, u[4 * i + 3], acc1);
        }
        float hn = tanhf(acc0 + acc1);
        hsh[cur ^ 1][bl][j] = hn;
        if (WS) {
            op[(size_t)t * B_ * H] = hn;
        } else if (t == T_ - 1) {
            op[0] = hn;   // h_last[b*H + j]
        }
        __syncthreads();
        cur ^= 1;
    }
}

// ---------------------------------------------------------------------------
// Dense (70 -> 5) + softmax. One thread per batch row.
// ---------------------------------------------------------------------------
__global__ void dense_softmax_kernel(const float* __restrict__ h,
                                     const float* __restrict__ Wd,
                                     const float* __restrict__ bd,
                                     float* __restrict__ out) {
    int b = blockIdx.x * blockDim.x + threadIdx.x;
    if (b >= B_) return;
    float l[5];
#pragma unroll
    for (int c = 0; c < 5; c++) l[c] = bd[c];
    for (int k = 0; k < 70; k++) {
        float hv = h[b * 70 + k];
#pragma unroll
        for (int c = 0; c < 5; c++) l[c] = fmaf(hv, Wd[k * 5 + c], l[c]);
    }
    float m = l[0];
#pragma unroll
    for (int c = 1; c < 5; c++) m = fmaxf(m, l[c]);
    float s = 0.f;
#pragma unroll
    for (int c = 0; c < 5; c++) { l[c] = expf(l[c] - m); s += l[c]; }
    float inv = 1.f / s;
#pragma unroll
    for (int c = 0; c < 5; c++) out[b * 5 + c] = l[c] * inv;
}

// ---------------------------------------------------------------------------
extern "C" void kernel_launch(void* const* d_in, const int* in_sizes, int n_in,
                              void* d_out, int out_size) {
    const float* x  = (const float*)d_in[0];
    const float* W0 = (const float*)d_in[1];
    const float* U0 = (const float*)d_in[2];
    const float* b0 = (const float*)d_in[3];
    const float* W1 = (const float*)d_in[4];
    const float* U1 = (const float*)d_in[5];
    const float* b1 = (const float*)d_in[6];
    const float* W2 = (const float*)d_in[7];
    const float* U2 = (const float*)d_in[8];
    const float* b2 = (const float*)d_in[9];
    const float* W3 = (const float*)d_in[10];
    const float* U3 = (const float*)d_in[11];
    const float* b3 = (const float*)d_in[12];
    const float* Wd = (const float*)d_in[13];
    const float* bd = (const float*)d_in[14];
    float* out = (float*)d_out;

    static float* bufA = nullptr;
    static float* bufB = nullptr;
    static float* hlast = nullptr;
    if (!bufA) {
        cudaGetSymbolAddress((void**)&bufA, g_bufA);
        cudaGetSymbolAddress((void**)&bufB, g_bufB);
        cudaGetSymbolAddress((void**)&hlast, g_hlast);
    }

    const int M = T_ * B_;  // 262144

    // Layer 0: x [B,T,78] -> xw0 [T,B,16]; scan -> hseq0 [T,B,16]
    gemm_kernel<78, 16, 128, true><<<M / 128, 4 * 32>>>(x, W0, b0, bufA);
    scan_kernel<16, 4, true><<<B_ / 4, 4 * 16>>>(bufA, U0, bufB);

    // Layer 1: hseq0 -> xw1 [T,B,32]; scan -> hseq1
    gemm_kernel<16, 32, 128, false><<<M / 128, 8 * 32>>>(bufB, W1, b1, bufA);
    scan_kernel<32, 4, true><<<B_ / 4, 4 * 32>>>(bufA, U1, bufB);

    // Layer 2: hseq1 -> xw2 [T,B,64]; scan -> hseq2
    gemm_kernel<32, 64, 128, false><<<M / 128, 16 * 32>>>(bufB, W2, b2, bufA);
    scan_kernel<64, 4, true><<<B_ / 4, 4 * 64>>>(bufA, U2, bufB);

    // Layer 3: hseq2 -> xw3 [T,B,70]; scan -> h_last [B,70]
    gemm_kernel<64, 70, 64, false><<<M / 64, 18 * 16>>>(bufB, W3, b3, bufA);
    scan_kernel<70, 4, false><<<B_ / 4, 4 * 70>>>(bufA, U3, hlast);

    // Dense + softmax
    dense_softmax_kernel<<<2, 256>>>(hlast, Wd, bd, out);
}

// round 2
// speedup vs baseline: 1.0039x; 1.0039x over previous
#include <cuda_runtime.h>
#include <math.h>

#define B_ 512
#define T_ 512

// Scratch (static __device__ arrays: allocation-free per harness rules)
__device__ float g_bufA[(size_t)T_ * B_ * 70];   // xw of current layer
__device__ float g_bufB[(size_t)T_ * B_ * 64];   // hidden sequence of layers 0..2
__device__ float g_hlast[B_ * 70];

// ---------------------------------------------------------------------------
// helpers
// ---------------------------------------------------------------------------
__device__ __forceinline__ float2 ffma2(float2 a, float2 b, float2 c) {
    float2 d;
    asm("fma.rn.f32x2 %0, %1, %2, %3;"
        : "=l"(reinterpret_cast<unsigned long long&>(d))
        : "l"(reinterpret_cast<const unsigned long long&>(a)),
          "l"(reinterpret_cast<const unsigned long long&>(b)),
          "l"(reinterpret_cast<const unsigned long long&>(c)));
    return d;
}

// tanh(x) = sign(x) * (1 - e^{-2|x|}) / (1 + e^{-2|x|}); denom in [1,2] so
// __fdividef is safe; abs error ~1e-7.
__device__ __forceinline__ float ftanh(float x) {
    float ax = fabsf(x);
    float t = __expf(-2.f * ax);
    float r = __fdividef(1.f - t, 1.f + t);
    return copysignf(r, x);
}

// ---------------------------------------------------------------------------
// GEMM: out[r, n] = sum_k inrow(r)[k] * W[k][n] + bias[n],  r = t*B_ + b
// out is time-major [T, B, N]. For layer 0 (L0=true) the input is x [B, T, K].
// ---------------------------------------------------------------------------
template <int K, int N, int TM, bool L0>
__global__ void __launch_bounds__(((N + 3) / 4) * (TM / 4))
gemm_kernel(const float* __restrict__ in, const float* __restrict__ W,
            const float* __restrict__ bias, float* __restrict__ out) {
    constexpr int NG4 = (N + 3) / 4;   // float4 col groups
    constexpr int NP  = NG4 * 4;       // padded N
    constexpr int TMP = TM + 4;        // padded row stride (16B-aligned rows)

    __shared__ __align__(16) float AshT[K * TMP];  // [k][row]
    __shared__ __align__(16) float Wsh[K * NP];    // [k][col] padded

    const int tid  = threadIdx.x;
    const int nthr = blockDim.x;
    const int rM   = blockIdx.x * TM;

    for (int idx = tid; idx < K * NP; idx += nthr) {
        int k = idx / NP, c = idx % NP;
        Wsh[idx] = (c < N) ? W[k * N + c] : 0.f;
    }
    for (int idx = tid; idx < TM * K; idx += nthr) {
        int rr = idx / K, kk = idx % K;
        int r = rM + rr;
        size_t g;
        if (L0) {
            int t = r >> 9;          // r / B_
            int b = r & (B_ - 1);    // r % B_
            g = ((size_t)b * T_ + t) * K + kk;   // x is [B, T, K]
        } else {
            g = (size_t)r * K + kk;              // time-major [T*B, K]
        }
        AshT[kk * TMP + rr] = in[g];
    }
    __syncthreads();

    const int tx  = tid % NG4;       // col group
    const int rid = tid / NG4;       // row group (4 rows)
    const int colb = 4 * tx;

    float4 bv;
    bv.x = (colb + 0 < N) ? bias[colb + 0] : 0.f;
    bv.y = (colb + 1 < N) ? bias[colb + 1] : 0.f;
    bv.z = (colb + 2 < N) ? bias[colb + 2] : 0.f;
    bv.w = (colb + 3 < N) ? bias[colb + 3] : 0.f;
    float4 acc0 = bv, acc1 = bv, acc2 = bv, acc3 = bv;

    const float4* Wp = (const float4*)Wsh;
#pragma unroll 4
    for (int k = 0; k < K; k++) {
        float4 a = *(const float4*)&AshT[k * TMP + rid * 4];
        float4 w = Wp[k * NG4 + tx];
        acc0.x = fmaf(a.x, w.x, acc0.x); acc0.y = fmaf(a.x, w.y, acc0.y);
        acc0.z = fmaf(a.x, w.z, acc0.z); acc0.w = fmaf(a.x, w.w, acc0.w);
        acc1.x = fmaf(a.y, w.x, acc1.x); acc1.y = fmaf(a.y, w.y, acc1.y);
        acc1.z = fmaf(a.y, w.z, acc1.z); acc1.w = fmaf(a.y, w.w, acc1.w);
        acc2.x = fmaf(a.z, w.x, acc2.x); acc2.y = fmaf(a.z, w.y, acc2.y);
        acc2.z = fmaf(a.z, w.z, acc2.z); acc2.w = fmaf(a.z, w.w, acc2.w);
        acc3.x = fmaf(a.w, w.x, acc3.x); acc3.y = fmaf(a.w, w.y, acc3.y);
        acc3.z = fmaf(a.w, w.z, acc3.z); acc3.w = fmaf(a.w, w.w, acc3.w);
    }

    float4 accs[4] = {acc0, acc1, acc2, acc3};
#pragma unroll
    for (int r = 0; r < 4; r++) {
        size_t row = (size_t)(rM + rid * 4 + r);
        if constexpr (N % 4 == 0) {
            *(float4*)&out[row * N + colb] = accs[r];
        } else {
            float v[4] = {accs[r].x, accs[r].y, accs[r].z, accs[r].w};
#pragma unroll
            for (int c = 0; c < 4; c++)
                if (colb + c < N) out[row * N + colb + c] = v[c];
        }
    }
}

// ---------------------------------------------------------------------------
// Recurrent scan v2: h_t = tanh(xw_t + h_{t-1} @ U), h_0 = 0.
// Packed over a pair of batch elements (fma.rn.f32x2). Thread = (pair, unit j,
// half). SPLIT=2 splits the dot product over two adjacent lanes (shfl_xor
// combine). xw prefetched 2 timesteps ahead. H is padded (mult of 4), HV valid.
// ---------------------------------------------------------------------------
template <int H, int HV, int NPAIR, int SPLIT, bool WS>
__global__ void __launch_bounds__(NPAIR * H * SPLIT)
scan2_kernel(const float* __restrict__ xw, const float* __restrict__ U,
             float* __restrict__ out) {
    constexpr int NTHR = NPAIR * H * SPLIT;
    constexpr int NU = H / SPLIT;          // units handled per half
    __shared__ __align__(16) float2 hsh[2][NPAIR][H];

    const int tid  = threadIdx.x;
    const int half = (SPLIT == 2) ? (tid & 1) : 0;
    const int rest = (SPLIT == 2) ? (tid >> 1) : tid;
    const int j    = rest % H;
    const int pair = rest / H;
    const int b0   = (blockIdx.x * NPAIR + pair) * 2;
    const bool jv  = (j < HV);

    // u2[k] = {U[i][j], U[i][j]}, i = half*NU + k  (zero padded)
    float2 u2[NU];
#pragma unroll
    for (int k = 0; k < NU; k++) {
        int i = half * NU + k;
        float v = (jv && i < HV) ? U[i * HV + j] : 0.f;
        u2[k] = make_float2(v, v);
    }

    for (int idx = tid; idx < 2 * NPAIR * H; idx += NTHR)
        ((float2*)hsh)[idx] = make_float2(0.f, 0.f);
    if (NTHR <= 32) __syncwarp(); else __syncthreads();

    const float* xp = xw + (size_t)b0 * HV + j;

    // prefetch pipeline (depth 2)
    float2 x0 = make_float2(0.f, 0.f), x1 = make_float2(0.f, 0.f);
    if (jv) {
        x0 = make_float2(xp[0], xp[HV]);
        size_t o1 = (size_t)B_ * HV;
        x1 = make_float2(xp[o1], xp[o1 + HV]);
    }

    int cur = 0;
    for (int t = 0; t < T_; t++) {
        float2 x2 = make_float2(0.f, 0.f);
        if (jv && t + 2 < T_) {
            size_t o = (size_t)(t + 2) * B_ * HV;
            x2 = make_float2(xp[o], xp[o + HV]);
        }

        float2 a0 = (half == 0) ? x0 : make_float2(0.f, 0.f);
        float2 a1 = make_float2(0.f, 0.f);
        float2 a2 = make_float2(0.f, 0.f);
        float2 a3 = make_float2(0.f, 0.f);
        const float4* hp = (const float4*)&hsh[cur][pair][half * NU];
#pragma unroll
        for (int k = 0; k < NU / 2; k += 2) {
            float4 hv = hp[k];
            a0 = ffma2(make_float2(hv.x, hv.y), u2[2 * k + 0], a0);
            a1 = ffma2(make_float2(hv.z, hv.w), u2[2 * k + 1], a1);
            float4 hw = hp[k + 1];
            a2 = ffma2(make_float2(hw.x, hw.y), u2[2 * k + 2], a2);
            a3 = ffma2(make_float2(hw.z, hw.w), u2[2 * k + 3], a3);
        }

        float sx = (a0.x + a1.x) + (a2.x + a3.x);
        float sy = (a0.y + a1.y) + (a2.y + a3.y);
        if (SPLIT == 2) {
            sx += __shfl_xor_sync(0xffffffffu, sx, 1);
            sy += __shfl_xor_sync(0xffffffffu, sy, 1);
        }
        float hn0 = ftanh(sx);
        float hn1 = ftanh(sy);

        if (half == 0) {
            hsh[cur ^ 1][pair][j] = make_float2(hn0, hn1);
            if (WS) {
                if (jv) {
                    size_t o = ((size_t)t * B_ + b0) * HV + j;
                    out[o] = hn0;
                    out[o + HV] = hn1;
                }
            } else if (t == T_ - 1 && jv) {
                out[(size_t)b0 * HV + j] = hn0;
                out[(size_t)(b0 + 1) * HV + j] = hn1;
            }
        }
        if (NTHR <= 32) __syncwarp(); else __syncthreads();
        x0 = x1; x1 = x2;
        cur ^= 1;
    }
}

// ---------------------------------------------------------------------------
// Dense (70 -> 5) + softmax. One thread per batch row.
// ---------------------------------------------------------------------------
__global__ void dense_softmax_kernel(const float* __restrict__ h,
                                     const float* __restrict__ Wd,
                                     const float* __restrict__ bd,
                                     float* __restrict__ out) {
    int b = blockIdx.x * blockDim.x + threadIdx.x;
    if (b >= B_) return;
    float l[5];
#pragma unroll
    for (int c = 0; c < 5; c++) l[c] = bd[c];
    for (int k = 0; k < 70; k++) {
        float hv = h[b * 70 + k];
#pragma unroll
        for (int c = 0; c < 5; c++) l[c] = fmaf(hv, Wd[k * 5 + c], l[c]);
    }
    float m = l[0];
#pragma unroll
    for (int c = 1; c < 5; c++) m = fmaxf(m, l[c]);
    float s = 0.f;
#pragma unroll
    for (int c = 0; c < 5; c++) { l[c] = expf(l[c] - m); s += l[c]; }
    float inv = 1.f / s;
#pragma unroll
    for (int c = 0; c < 5; c++) out[b * 5 + c] = l[c] * inv;
}

// ---------------------------------------------------------------------------
extern "C" void kernel_launch(void* const* d_in, const int* in_sizes, int n_in,
                              void* d_out, int out_size) {
    const float* x  = (const float*)d_in[0];
    const float* W0 = (const float*)d_in[1];
    const float* U0 = (const float*)d_in[2];
    const float* b0 = (const float*)d_in[3];
    const float* W1 = (const float*)d_in[4];
    const float* U1 = (const float*)d_in[5];
    const float* b1 = (const float*)d_in[6];
    const float* W2 = (const float*)d_in[7];
    const float* U2 = (const float*)d_in[8];
    const float* b2 = (const float*)d_in[9];
    const float* W3 = (const float*)d_in[10];
    const float* U3 = (const float*)d_in[11];
    const float* b3 = (const float*)d_in[12];
    const float* Wd = (const float*)d_in[13];
    const float* bd = (const float*)d_in[14];
    float* out = (float*)d_out;

    static float* bufA = nullptr;
    static float* bufB = nullptr;
    static float* hlast = nullptr;
    if (!bufA) {
        cudaGetSymbolAddress((void**)&bufA, g_bufA);
        cudaGetSymbolAddress((void**)&bufB, g_bufB);
        cudaGetSymbolAddress((void**)&hlast, g_hlast);
    }

    const int M = T_ * B_;  // 262144

    // Layer 0: x [B,T,78] -> xw0 [T,B,16]; scan -> hseq0 [T,B,16]
    gemm_kernel<78, 16, 128, true><<<M / 128, 4 * 32>>>(x, W0, b0, bufA);
    scan2_kernel<16, 16, 2, 1, true><<<B_ / 4, 32>>>(bufA, U0, bufB);

    // Layer 1: hseq0 -> xw1 [T,B,32]; scan -> hseq1
    gemm_kernel<16, 32, 128, false><<<M / 128, 8 * 32>>>(bufB, W1, b1, bufA);
    scan2_kernel<32, 32, 1, 1, true><<<B_ / 2, 32>>>(bufA, U1, bufB);

    // Layer 2: hseq1 -> xw2 [T,B,64]; scan -> hseq2
    gemm_kernel<32, 64, 128, false><<<M / 128, 16 * 32>>>(bufB, W2, b2, bufA);
    scan2_kernel<64, 64, 2, 2, true><<<B_ / 4, 256>>>(bufA, U2, bufB);

    // Layer 3: hseq2 -> xw3 [T,B,70]; scan -> h_last [B,70]
    gemm_kernel<64, 70, 64, false><<<M / 64, 18 * 16>>>(bufB, W3, b3, bufA);
    scan2_kernel<72, 70, 2, 2, false><<<B_ / 4, 288>>>(bufA, U3, hlast);

    // Dense + softmax
    dense_softmax_kernel<<<2, 256>>>(hlast, Wd, bd, out);
}